// round 7
// baseline (speedup 1.0000x reference)
#include <cuda_runtime.h>
#include <math.h>

// Problem constants (match reference)
#define T_STEPS 1024
#define B_SIZE  32768
#define G1      50
#define H1      32
#define G2      20
#define NBLOCKS 512

// Device globals (no allocation allowed)
__device__ float g_cbeta[T_STEPS];
__device__ int   g_arrive = 0;

// ---------------------------------------------------------------------------
// Fused kernel: phase 1 — each of 512 co-resident blocks computes 2 betas
// (factorized layer-2 RBF: 3 exps per (t,i) instead of 20); grid barrier;
// phase 2 — the 1024-step Euler SIR scan (proven-optimal R3/R6 form).
//
// Grid-barrier safety: 512 blocks x 64 thr, ~4.5KB smem, <=48 regs -> the
// whole grid is resident in one wave, so spinning on the arrival counter
// cannot deadlock. Block 0 resets the counter at kernel end; all spinners
// exit the barrier ~46K cycles before that reset (scan length), and graph
// replays are stream-ordered, so every launch starts with g_arrive == 0.
// ---------------------------------------------------------------------------
__global__ void __launch_bounds__(64)
fused_kan_sir_kernel(const float* __restrict__ t_steps,
                     const float* __restrict__ initial_I,
                     const float* __restrict__ grid1,
                     const float* __restrict__ spline_w1, // [50,32]
                     const float* __restrict__ base_w1,   // [32]
                     const float* __restrict__ grid2,
                     const float* __restrict__ spline_w2, // [32,20]
                     const float* __restrict__ base_w2,   // [32]
                     const float* __restrict__ gamma_param,
                     float* __restrict__ out)
{
    __shared__ float basis1[G1];
    __shared__ float hsm[H1];
    __shared__ float C2[G2];
    __shared__ float scb[T_STEPS + 8];

    const int tid = threadIdx.x;

    // ---- Phase 1: betas for t in {2*bid, 2*bid+1} ----
    // C2[k] = exp(-10*(grid2[k]-0.5)^2) — shared across both t's
    if (tid >= 44) {
        int k = tid - 44;
        float v = grid2[k] - 0.5f;
        C2[k] = __expf(-10.0f * v * v);
    }

    const float dt = t_steps[1] - t_steps[0];

    #pragma unroll
    for (int s = 0; s < 2; s++) {
        const int t   = blockIdx.x * 2 + s;
        const float x = t_steps[t];

        if (tid < G1) {
            float d = x - grid1[tid];
            basis1[tid] = __expf(-10.0f * d * d);
        }
        __syncthreads();

        if (tid < H1) {
            float acc = x * base_w1[tid];
            #pragma unroll
            for (int g = 0; g < G1; g++)
                acc = fmaf(basis1[g], spline_w1[g * H1 + tid], acc);
            hsm[tid] = acc;
        }
        __syncthreads();

        if (tid < H1) {
            const float h  = hsm[tid];
            float u = fminf(fmaxf(h - 0.5f, -2.5f), 2.5f); // clamp: basis ~0 there
            const float v0 = grid2[0] - 0.5f;
            const float dv = grid2[1] - grid2[0];
            const float e0 = __expf(-10.0f * u * u);
            float       tk = __expf(20.0f * u * v0);
            const float f  = __expf(20.0f * u * dv);

            float acc = 0.0f;
            #pragma unroll
            for (int k = 0; k < G2; k++) {
                acc = fmaf(tk * C2[k], spline_w2[tid * G2 + k], acc);
                tk *= f;
            }
            acc = fmaf(h, base_w2[tid], e0 * acc);

            #pragma unroll
            for (int o = 16; o > 0; o >>= 1)
                acc += __shfl_down_sync(0xFFFFFFFFu, acc, o);

            if (tid == 0) {
                float beta = fmaxf(acc, 0.0f) + log1pf(expf(-fabsf(acc)));
                g_cbeta[t] = dt * beta;
            }
        }
        __syncthreads();
    }

    // ---- Grid barrier ----
    if (tid == 0) {
        __threadfence();                       // publish g_cbeta
        atomicAdd(&g_arrive, 1);
        while (atomicAdd(&g_arrive, 0) < NBLOCKS) { }
    }
    __syncthreads();

    // ---- Phase 2: load all betas to smem, run the scan ----
    #pragma unroll
    for (int i = 0; i < T_STEPS / 64; i++)
        scb[tid + i * 64] = __ldcg(&g_cbeta[tid + i * 64]);
    if (tid < 8) scb[T_STEPS + tid] = 0.0f;

    const int b = blockIdx.x * 64 + tid;
    float I = initial_I[b];
    float S = 1.0f - I;

    const float gp    = gamma_param[0];
    const float gamma = fmaxf(gp, 0.0f) + log1pf(expf(-fabsf(gp)));
    const float a     = 1.0f - dt * gamma;   // I' = I*a + ni

    __syncthreads();

    float* outp = out + b;
    float cb = scb[0];
    #pragma unroll 8
    for (int t = 0; t < T_STEPS; t++) {
        const float cb_n = scb[t + 1];       // prefetch next beta
        const float ni = cb * (S * I);       // dt * new_infections
        I = fmaf(I, a, ni);                  // clips removed: state stays in [0,1]
        S = S - ni;
        outp[(size_t)t * B_SIZE] = I;
        cb = cb_n;
    }

    // ---- Reset barrier counter for the next replay ----
    if (blockIdx.x == 0 && tid == 0) {
        __threadfence();
        g_arrive = 0;
    }
}

// ---------------------------------------------------------------------------
// Inputs (metadata order):
// 0: t_steps [1024], 1: initial_I [32768], 2: grid1 [50], 3: spline_w1 [1600],
// 4: base_w1 [32], 5: grid2 [20], 6: spline_w2 [640], 7: base_w2 [32],
// 8: gamma_param [1]
// ---------------------------------------------------------------------------
extern "C" void kernel_launch(void* const* d_in, const int* in_sizes, int n_in,
                              void* d_out, int out_size)
{
    const float* t_steps    = (const float*)d_in[0];
    const float* initial_I  = (const float*)d_in[1];
    const float* grid1      = (const float*)d_in[2];
    const float* spline_w1  = (const float*)d_in[3];
    const float* base_w1    = (const float*)d_in[4];
    const float* grid2      = (const float*)d_in[5];
    const float* spline_w2  = (const float*)d_in[6];
    const float* base_w2    = (const float*)d_in[7];
    const float* gamma_p    = (const float*)d_in[8];
    float* out              = (float*)d_out;

    fused_kan_sir_kernel<<<NBLOCKS, 64>>>(t_steps, initial_I, grid1,
                                          spline_w1, base_w1, grid2,
                                          spline_w2, base_w2, gamma_p, out);
}

// round 8
// speedup vs baseline: 1.0235x; 1.0235x over previous
#include <cuda_runtime.h>
#include <math.h>

// Problem constants (match reference)
#define T_STEPS 1024
#define B_SIZE  32768
#define G1      50
#define H1      32
#define G2      20
#define NBLOCKS 512

// Device globals (no allocation allowed)
__device__ float        g_cbeta[T_STEPS];
__device__ volatile int g_arrive = 0;

// ---------------------------------------------------------------------------
// Fused kernel. Phase 1: warp w of each block computes beta(2*bid + w) —
// fully warp-local (no block syncs), factorized layer-2 RBF (3 exps/(t,i)).
// Grid barrier: one atomicAdd arrival per block, spin on a PLAIN L2 load
// (no atomic-ALU serialization). Phase 2: the proven 24.5us Euler SIR scan.
//
// Residency: 512 blocks x 64 thr, ~4.6KB smem, 32-40 regs -> 4 blocks/SM,
// whole grid in one wave -> spin barrier cannot deadlock. Block 0 resets the
// counter after its scan (~46K cyc after every spinner has exited); graph
// replays are stream-ordered, so each launch starts with g_arrive == 0.
// ---------------------------------------------------------------------------
__global__ void __launch_bounds__(64)
fused_kan_sir_kernel(const float* __restrict__ t_steps,
                     const float* __restrict__ initial_I,
                     const float* __restrict__ grid1,
                     const float* __restrict__ spline_w1, // [50,32]
                     const float* __restrict__ base_w1,   // [32]
                     const float* __restrict__ grid2,
                     const float* __restrict__ spline_w2, // [32,20]
                     const float* __restrict__ base_w2,   // [32]
                     const float* __restrict__ gamma_param,
                     float* __restrict__ out)
{
    __shared__ float sbasis[2][G1];      // per-warp layer-1 basis
    __shared__ float C2[G2];
    __shared__ float scb[T_STEPS + 8];

    const int tid  = threadIdx.x;
    const int w    = tid >> 5;           // warp id (0,1)
    const int lane = tid & 31;

    // ---- Prefetch scan inputs early (latency hides under phase 1) ----
    const int   b   = blockIdx.x * 64 + tid;
    const float I_init = initial_I[b];
    const float gp     = gamma_param[0];
    const float dt     = t_steps[1] - t_steps[0];

    // ---- Phase 1: beta(t), t = 2*bid + w, one warp per t ----
    {
        const int   t = blockIdx.x * 2 + w;
        const float x = t_steps[t];

        // layer-1 basis: 50 exps per warp (lanes 0..17 do two)
        {
            float d = x - grid1[lane];
            sbasis[w][lane] = __expf(-10.0f * d * d);
            if (lane < G1 - 32) {
                float d2 = x - grid1[lane + 32];
                sbasis[w][lane + 32] = __expf(-10.0f * d2 * d2);
            }
        }
        // C2 table (both warps write identical values — benign)
        if (lane < G2) {
            float v = grid2[lane] - 0.5f;
            C2[lane] = __expf(-10.0f * v * v);
        }
        __syncwarp();

        // h[lane] = x*base_w1 + sum_g basis[g]*w1[g][lane]  (2 accumulators)
        float acc0 = x * base_w1[lane];
        float acc1 = 0.0f;
        #pragma unroll
        for (int g = 0; g < G1 - 1; g += 2) {
            acc0 = fmaf(sbasis[w][g],     spline_w1[g * H1 + lane],       acc0);
            acc1 = fmaf(sbasis[w][g + 1], spline_w1[(g + 1) * H1 + lane], acc1);
        }
        const float h = fmaf(sbasis[w][G1 - 1], spline_w1[(G1 - 1) * H1 + lane],
                             acc0 + acc1);

        // layer-2 factorized RBF
        float u = fminf(fmaxf(h - 0.5f, -2.5f), 2.5f);  // clamp: basis ~0 there
        const float v0 = grid2[0] - 0.5f;
        const float dv = grid2[1] - grid2[0];
        const float e0 = __expf(-10.0f * u * u);
        float       tk = __expf(20.0f * u * v0);
        const float f  = __expf(20.0f * u * dv);

        float acc = 0.0f;
        #pragma unroll
        for (int k = 0; k < G2; k++) {
            acc = fmaf(tk * C2[k], spline_w2[lane * G2 + k], acc);
            tk *= f;
        }
        acc = fmaf(h, base_w2[lane], e0 * acc);

        #pragma unroll
        for (int o = 16; o > 0; o >>= 1)
            acc += __shfl_down_sync(0xFFFFFFFFu, acc, o);

        if (lane == 0) {
            float e    = __expf(-fabsf(acc));
            float beta = fmaxf(acc, 0.0f) + __logf(1.0f + e);  // softplus
            g_cbeta[t] = dt * beta;
        }
    }

    // ---- Grid barrier: atomic arrive, plain-load spin ----
    __syncthreads();
    if (tid == 0) {
        __threadfence();                         // publish g_cbeta
        atomicAdd((int*)&g_arrive, 1);
        while (g_arrive < NBLOCKS) { }           // volatile L2 load, no atomics
    }
    __syncthreads();

    // ---- Phase 2: betas -> smem, run the scan ----
    #pragma unroll
    for (int i = 0; i < T_STEPS / 64; i++)
        scb[tid + i * 64] = __ldcg(&g_cbeta[tid + i * 64]);
    if (tid < 8) scb[T_STEPS + tid] = 0.0f;

    float I = I_init;
    float S = 1.0f - I;
    const float gamma = fmaxf(gp, 0.0f) + log1pf(expf(-fabsf(gp)));
    const float a     = 1.0f - dt * gamma;       // I' = I*a + ni

    __syncthreads();

    float* outp = out + b;
    float cb = scb[0];
    #pragma unroll 8
    for (int t = 0; t < T_STEPS; t++) {
        const float cb_n = scb[t + 1];           // prefetch next beta
        const float ni = cb * (S * I);           // dt * new_infections
        I = fmaf(I, a, ni);                      // clips removed: state in [0,1]
        S = S - ni;
        outp[(size_t)t * B_SIZE] = I;
        cb = cb_n;
    }

    // ---- Reset barrier counter for the next replay ----
    if (blockIdx.x == 0 && tid == 0) {
        __threadfence();
        g_arrive = 0;
    }
}

// ---------------------------------------------------------------------------
// Inputs (metadata order):
// 0: t_steps [1024], 1: initial_I [32768], 2: grid1 [50], 3: spline_w1 [1600],
// 4: base_w1 [32], 5: grid2 [20], 6: spline_w2 [640], 7: base_w2 [32],
// 8: gamma_param [1]
// ---------------------------------------------------------------------------
extern "C" void kernel_launch(void* const* d_in, const int* in_sizes, int n_in,
                              void* d_out, int out_size)
{
    const float* t_steps    = (const float*)d_in[0];
    const float* initial_I  = (const float*)d_in[1];
    const float* grid1      = (const float*)d_in[2];
    const float* spline_w1  = (const float*)d_in[3];
    const float* base_w1    = (const float*)d_in[4];
    const float* grid2      = (const float*)d_in[5];
    const float* spline_w2  = (const float*)d_in[6];
    const float* base_w2    = (const float*)d_in[7];
    const float* gamma_p    = (const float*)d_in[8];
    float* out              = (float*)d_out;

    fused_kan_sir_kernel<<<NBLOCKS, 64>>>(t_steps, initial_I, grid1,
                                          spline_w1, base_w1, grid2,
                                          spline_w2, base_w2, gamma_p, out);
}